// round 6
// baseline (speedup 1.0000x reference)
#include <cuda_runtime.h>
#include <mma.h>
#include <math.h>

using namespace nvcuda;

#define N_NODES 40000
#define PAD_N   40064            // 313 * 128
#define N_EDGES 640000
#define DIM     128
#define QKV_LD  384
#define HID     512
#define LN_EPS  1e-5f

// ---------------- scratch (device globals; no allocation allowed) ----------
static __device__ float g_qkv[(size_t)PAD_N * QKV_LD];  // [q|k|v] per node
static __device__ float g_rst[(size_t)PAD_N * DIM];     // post-LN1
static __device__ float g_h  [(size_t)PAD_N * HID];     // FFN hidden
static __device__ int   g_off[N_NODES + 1];             // CSR offsets (by dst)
static __device__ int   g_cur[N_NODES];                 // counts / cursors
static __device__ int   g_esrc[N_EDGES];                // src node ids sorted by dst
static __device__ int   g_part[256];                    // scan partials

// ---------------- cp.async helpers -----------------------------------------
__device__ __forceinline__ void cp16(float* smem, const float* gmem)
{
    unsigned s = (unsigned)__cvta_generic_to_shared(smem);
    asm volatile("cp.async.ca.shared.global [%0], [%1], 16;\n" :: "r"(s), "l"(gmem));
}
__device__ __forceinline__ void cp16z(float* smem, const float* gmem, bool pred)
{
    unsigned s = (unsigned)__cvta_generic_to_shared(smem);
    int sz = pred ? 16 : 0;   // src-size 0 => zero-fill 16B, no gmem access
    asm volatile("cp.async.ca.shared.global [%0], [%1], 16, %2;\n"
                 :: "r"(s), "l"(gmem), "r"(sz));
}
#define CP_COMMIT() asm volatile("cp.async.commit_group;\n" ::)
#define CP_WAIT(n)  asm volatile("cp.async.wait_group %0;\n" :: "n"(n))

// ---------------- TF32 WMMA GEMM: C[M,N] = A[M,K] @ B[K,N] (row-major) -----
// Tile: BM=128, BN=128, BK=32, 3-stage cp.async, 2 blocks/SM.
// 4 warps in 2x2; warp tile 64x64 (4x4 wmma 16x16x8) -> 16 MMA per 8 loads.
// EPI: 0 = plain store (QKV: B selected by blockIdx.z, C col offset z*128)
//      1 = +bias then PReLU
//      2 = +bias +residual, then per-row LayerNorm -> final output (row guard)
#define GBM 128
#define GBN 128
#define GBK 32
#define NSTG 3
#define AS_F (GBM * 36)    // 4608 floats / stage
#define BS_F (GBK * 132)   // 4224 floats / stage
#define SMEM_BYTES (NSTG * (AS_F + BS_F) * 4)   // 105984 B

template <int EPI>
__global__ __launch_bounds__(128, 2)
void mm_tf32_kernel(const float* __restrict__ A, int lda, int Mlim,
                    const float* __restrict__ B0,
                    const float* __restrict__ B1,
                    const float* __restrict__ B2, int ldb,
                    float* __restrict__ C, int ldc, int K,
                    const float* __restrict__ bias,
                    const float* __restrict__ pw,
                    const float* __restrict__ res,
                    const float* __restrict__ lng,
                    const float* __restrict__ lnb)
{
    extern __shared__ __align__(16) float sm[];
    float (*Cs)[132] = (float(*)[132]) sm;        // epilogue reuse (128x132)

    const int tid = threadIdx.x;
    const int wid = tid >> 5;
    const int rowBase = blockIdx.x * GBM;
    const int colBaseB = blockIdx.y * GBN;
    const int z = blockIdx.z;
    const float* B = (z == 0) ? B0 : (z == 1) ? B1 : B2;
    const int colBaseC = colBaseB + z * 128;

    const int wm = wid >> 1;            // 0..1 -> warp row0 = wm*64
    const int wn = wid & 1;             // 0..1 -> warp col0 = wn*64

    wmma::fragment<wmma::accumulator, 16, 16, 8, float> acc[4][4];
#pragma unroll
    for (int i = 0; i < 4; i++)
#pragma unroll
        for (int j = 0; j < 4; j++) wmma::fill_fragment(acc[i][j], 0.f);

    const int ar = tid >> 3;            // 0..15 (8 passes of 16 rows)
    const int ac = (tid & 7) * 4;       // 0..28
    const int br = tid >> 5;            // 0..3  (8 passes of 4 rows)
    const int bc = (tid & 31) * 4;      // 0..124

    const float* Abase = A + (size_t)rowBase * lda;
    const float* Bbase = B + colBaseB;

    auto issue = [&](int st, int k0) {
        float* As = sm + st * (AS_F + BS_F);
        float* Bs = As + AS_F;
#pragma unroll
        for (int p = 0; p < 8; p++) {
            const int r = ar + p * 16;
            cp16z(As + r * 36 + ac, Abase + (size_t)r * lda + k0 + ac,
                  rowBase + r < Mlim);
        }
#pragma unroll
        for (int p = 0; p < 8; p++) {
            const int r = br + p * 4;
            cp16(Bs + r * 132 + bc, Bbase + (size_t)(k0 + r) * ldb + bc);
        }
        CP_COMMIT();
    };

    const int nIter = K / GBK;          // 4 or 16
    issue(0, 0);
    issue(1, GBK);
    int st = 0;                          // stage of iter 'it'
    int nx = 2;                          // next stage to fill

    for (int it = 0; it < nIter; it++) {
        if (it + 2 < nIter) {
            issue(nx, (it + 2) * GBK);
            CP_WAIT(2);
        } else if (it + 1 < nIter) {
            CP_WAIT(1);
        } else {
            CP_WAIT(0);
        }
        __syncthreads();

        const float* As = sm + st * (AS_F + BS_F);
        const float* Bs = As + AS_F;
#pragma unroll
        for (int kk = 0; kk < GBK; kk += 8) {
            wmma::fragment<wmma::matrix_a, 16, 16, 8, wmma::precision::tf32, wmma::row_major> fa[4];
            wmma::fragment<wmma::matrix_b, 16, 16, 8, wmma::precision::tf32, wmma::row_major> fb[4];
#pragma unroll
            for (int i = 0; i < 4; i++)
                wmma::load_matrix_sync(fa[i], As + (wm * 64 + i * 16) * 36 + kk, 36);
#pragma unroll
            for (int j = 0; j < 4; j++)
                wmma::load_matrix_sync(fb[j], Bs + kk * 132 + wn * 64 + j * 16, 132);
#pragma unroll
            for (int i = 0; i < 4; i++)
#pragma unroll
                for (int j = 0; j < 4; j++)
                    wmma::mma_sync(acc[i][j], fa[i], fb[j], acc[i][j]);
        }
        __syncthreads();
        st = (st + 1 == NSTG) ? 0 : st + 1;
        nx = (nx + 1 == NSTG) ? 0 : nx + 1;
    }

    // stage C tile in shared
#pragma unroll
    for (int i = 0; i < 4; i++)
#pragma unroll
        for (int j = 0; j < 4; j++)
            wmma::store_matrix_sync(&Cs[wm * 64 + i * 16][wn * 64 + j * 16],
                                    acc[i][j], 132, wmma::mem_row_major);
    __syncthreads();

    if (EPI == 0) {
#pragma unroll
        for (int it = 0; it < 32; it++) {
            const int lin = tid + it * 128;      // f4 index over 128x32
            const int r = lin >> 5, c4 = (lin & 31) * 4;
            *(float4*)(C + (size_t)(rowBase + r) * ldc + colBaseC + c4) =
                *(const float4*)&Cs[r][c4];
        }
    } else if (EPI == 1) {
#pragma unroll
        for (int it = 0; it < 32; it++) {
            const int lin = tid + it * 128;
            const int r = lin >> 5, c4 = (lin & 31) * 4;
            float4 v = *(const float4*)&Cs[r][c4];
            const float4 bi = *(const float4*)(bias + colBaseC + c4);
            const float4 pv = *(const float4*)(pw + colBaseC + c4);
            v.x += bi.x; v.y += bi.y; v.z += bi.z; v.w += bi.w;
            v.x = v.x >= 0.f ? v.x : pv.x * v.x;
            v.y = v.y >= 0.f ? v.y : pv.y * v.y;
            v.z = v.z >= 0.f ? v.z : pv.z * v.z;
            v.w = v.w >= 0.f ? v.w : pv.w * v.w;
            *(float4*)(C + (size_t)(rowBase + r) * ldc + colBaseC + c4) = v;
        }
    } else {  // EPI == 2 : +bias +residual, per-row LayerNorm -> out
        const int lane = tid & 31;
        const int col = lane * 4;
        const float4 bi = *(const float4*)(bias + col);
        const float4 g4 = *(const float4*)(lng + col);
        const float4 b4 = *(const float4*)(lnb + col);
#pragma unroll
        for (int rr = 0; rr < 32; rr++) {
            const int r = wid * 32 + rr;
            const int grow = rowBase + r;
            float4 v = *(const float4*)&Cs[r][col];
            const float4 rs = *(const float4*)(res + (size_t)grow * DIM + col);
            float x0 = v.x + bi.x + rs.x;
            float x1 = v.y + bi.y + rs.y;
            float x2 = v.z + bi.z + rs.z;
            float x3 = v.w + bi.w + rs.w;
            float sum = x0 + x1 + x2 + x3;
            float sq = x0 * x0 + x1 * x1 + x2 * x2 + x3 * x3;
#pragma unroll
            for (int o = 16; o; o >>= 1) {
                sum += __shfl_xor_sync(0xffffffffu, sum, o);
                sq  += __shfl_xor_sync(0xffffffffu, sq, o);
            }
            const float mu = sum * (1.f / DIM);
            const float var = sq * (1.f / DIM) - mu * mu;
            const float rstd = rsqrtf(var + LN_EPS);
            float4 o4;
            o4.x = (x0 - mu) * rstd * g4.x + b4.x;
            o4.y = (x1 - mu) * rstd * g4.y + b4.y;
            o4.z = (x2 - mu) * rstd * g4.z + b4.z;
            o4.w = (x3 - mu) * rstd * g4.w + b4.w;
            if (grow < N_NODES)
                *(float4*)(C + (size_t)grow * DIM + col) = o4;
        }
    }
}

// ---------------- CSR construction -----------------------------------------
__global__ void hist_kernel(const int* __restrict__ dst, int e)
{
    int i = blockIdx.x * blockDim.x + threadIdx.x;
    if (i < e) atomicAdd(&g_cur[dst[i]], 1);
}

#define SB 256
#define NSB ((N_NODES + SB - 1) / SB)   // 157

__global__ __launch_bounds__(SB)
void scan_blk_kernel(int n)
{
    __shared__ int sh[SB];
    const int t = threadIdx.x;
    const int i = blockIdx.x * SB + t;
    const int v = (i < n) ? g_cur[i] : 0;
    sh[t] = v;
    __syncthreads();
    for (int o = 1; o < SB; o <<= 1) {
        int x = (t >= o) ? sh[t - o] : 0;
        __syncthreads();
        sh[t] += x;
        __syncthreads();
    }
    if (i < n) g_off[i] = sh[t] - v;
    if (t == SB - 1) g_part[blockIdx.x] = sh[t];
}

__global__ __launch_bounds__(SB)
void scan_part_kernel(int nb, int n)
{
    __shared__ int sh[SB];
    const int t = threadIdx.x;
    const int v = (t < nb) ? g_part[t] : 0;
    sh[t] = v;
    __syncthreads();
    for (int o = 1; o < SB; o <<= 1) {
        int x = (t >= o) ? sh[t - o] : 0;
        __syncthreads();
        sh[t] += x;
        __syncthreads();
    }
    if (t < nb) g_part[t] = sh[t] - v;
    if (t == SB - 1) g_off[n] = sh[t];
}

__global__ __launch_bounds__(SB)
void scan_add_kernel(int n)
{
    const int i = blockIdx.x * SB + threadIdx.x;
    if (i < n) {
        const int o = g_off[i] + g_part[blockIdx.x];
        g_off[i] = o;
        g_cur[i] = o;
    }
}

// stores SRC node id directly (drops one gather level in attention)
__global__ void scatter_kernel(const int* __restrict__ src,
                               const int* __restrict__ dst, int e)
{
    int i = blockIdx.x * blockDim.x + threadIdx.x;
    if (i < e) {
        int p = atomicAdd(&g_cur[dst[i]], 1);
        g_esrc[p] = src[i];
    }
}

// ---------------- attention (warp per dst node, online softmax) + LN1 ------
__device__ __forceinline__ void attn_step(float4 k4, float4 v4, float4 q4,
                                          float& m, float& s, float4& acc)
{
    float x = q4.x * k4.x + q4.y * k4.y + q4.z * k4.z + q4.w * k4.w;
    x += __shfl_xor_sync(0xffffffffu, x, 1);
    x += __shfl_xor_sync(0xffffffffu, x, 2);
    x *= 0.08838834764831845f;              // 1/sqrt(DH*H) = 1/sqrt(128)
    const float nm = fmaxf(m, x);
    const float corr = __expf(m - nm);
    const float w = __expf(x - nm);
    s = s * corr + w;
    acc.x = acc.x * corr + w * v4.x;
    acc.y = acc.y * corr + w * v4.y;
    acc.z = acc.z * corr + w * v4.z;
    acc.w = acc.w * corr + w * v4.w;
    m = nm;
}

__global__ __launch_bounds__(256)
void attn_ln1_kernel(const float* __restrict__ feat,
                     const float* __restrict__ ln1g,
                     const float* __restrict__ ln1b)
{
    const int gw = (blockIdx.x * blockDim.x + threadIdx.x) >> 5;
    if (gw >= N_NODES) return;
    const int lane = threadIdx.x & 31;
    const int col = lane * 4;

    const float4 q4 = *(const float4*)(g_qkv + (size_t)gw * QKV_LD + col);

    float m = -INFINITY, s = 0.f;
    float4 acc = make_float4(0, 0, 0, 0);

    const int beg = g_off[gw], end = g_off[gw + 1];
    int t = beg;
    for (; t + 4 <= end; t += 4) {
        const int s0 = g_esrc[t],     s1 = g_esrc[t + 1];
        const int s2 = g_esrc[t + 2], s3 = g_esrc[t + 3];
        const float* b0 = g_qkv + (size_t)s0 * QKV_LD + col;
        const float* b1 = g_qkv + (size_t)s1 * QKV_LD + col;
        const float* b2 = g_qkv + (size_t)s2 * QKV_LD + col;
        const float* b3 = g_qkv + (size_t)s3 * QKV_LD + col;
        const float4 k0 = *(const float4*)(b0 + DIM);
        const float4 k1 = *(const float4*)(b1 + DIM);
        const float4 k2 = *(const float4*)(b2 + DIM);
        const float4 k3 = *(const float4*)(b3 + DIM);
        const float4 v0 = *(const float4*)(b0 + 2 * DIM);
        const float4 v1 = *(const float4*)(b1 + 2 * DIM);
        const float4 v2 = *(const float4*)(b2 + 2 * DIM);
        const float4 v3 = *(const float4*)(b3 + 2 * DIM);
        attn_step(k0, v0, q4, m, s, acc);
        attn_step(k1, v1, q4, m, s, acc);
        attn_step(k2, v2, q4, m, s, acc);
        attn_step(k3, v3, q4, m, s, acc);
    }
    for (; t < end; t++) {
        const float* b = g_qkv + (size_t)g_esrc[t] * QKV_LD + col;
        const float4 k4 = *(const float4*)(b + DIM);
        const float4 v4 = *(const float4*)(b + 2 * DIM);
        attn_step(k4, v4, q4, m, s, acc);
    }

    const float inv = (s > 0.f) ? (1.f / s) : 0.f;
    const float4 f4 = *(const float4*)(feat + (size_t)gw * DIM + col);
    float x0 = acc.x * inv + f4.x;
    float x1 = acc.y * inv + f4.y;
    float x2 = acc.z * inv + f4.z;
    float x3 = acc.w * inv + f4.w;

    float sum = x0 + x1 + x2 + x3;
    float sq = x0 * x0 + x1 * x1 + x2 * x2 + x3 * x3;
#pragma unroll
    for (int o = 16; o; o >>= 1) {
        sum += __shfl_xor_sync(0xffffffffu, sum, o);
        sq  += __shfl_xor_sync(0xffffffffu, sq, o);
    }
    const float mu = sum * (1.f / DIM);
    const float var = sq * (1.f / DIM) - mu * mu;
    const float rstd = rsqrtf(var + LN_EPS);

    const float4 g4 = *(const float4*)(ln1g + col);
    const float4 b4 = *(const float4*)(ln1b + col);
    float4 o4;
    o4.x = (x0 - mu) * rstd * g4.x + b4.x;
    o4.y = (x1 - mu) * rstd * g4.y + b4.y;
    o4.z = (x2 - mu) * rstd * g4.z + b4.z;
    o4.w = (x3 - mu) * rstd * g4.w + b4.w;
    *(float4*)(g_rst + (size_t)gw * DIM + col) = o4;
}

// ---------------- launch -----------------------------------------------------
extern "C" void kernel_launch(void* const* d_in, const int* in_sizes, int n_in,
                              void* d_out, int out_size)
{
    const float* feat  = (const float*)d_in[0];
    const int*   src   = (const int*)d_in[1];
    const int*   dst   = (const int*)d_in[2];
    const float* Wq    = (const float*)d_in[3];
    const float* Wk    = (const float*)d_in[4];
    const float* Wv    = (const float*)d_in[5];
    const float* ln1g  = (const float*)d_in[6];
    const float* ln1b  = (const float*)d_in[7];
    const float* ln2g  = (const float*)d_in[8];
    const float* ln2b  = (const float*)d_in[9];
    const float* W1    = (const float*)d_in[10];
    const float* b1    = (const float*)d_in[11];
    const float* prelu = (const float*)d_in[12];
    const float* W2    = (const float*)d_in[13];
    const float* b2    = (const float*)d_in[14];
    float* out = (float*)d_out;

    const int E = in_sizes[1];
    const int GX = PAD_N / GBM;   // 313

    void* p;
    float *qkv, *rst, *hbuf;
    int* curp;
    cudaGetSymbolAddress(&p, g_qkv); qkv  = (float*)p;
    cudaGetSymbolAddress(&p, g_rst); rst  = (float*)p;
    cudaGetSymbolAddress(&p, g_h);   hbuf = (float*)p;
    cudaGetSymbolAddress(&p, g_cur); curp = (int*)p;

    static bool init_done = false;
    static cudaStream_t s_side;
    static cudaEvent_t ev_fork, ev_join;
    if (!init_done) {
        cudaStreamCreateWithFlags(&s_side, cudaStreamNonBlocking);
        cudaEventCreateWithFlags(&ev_fork, cudaEventDisableTiming);
        cudaEventCreateWithFlags(&ev_join, cudaEventDisableTiming);
        cudaFuncSetAttribute(mm_tf32_kernel<0>, cudaFuncAttributeMaxDynamicSharedMemorySize, SMEM_BYTES);
        cudaFuncSetAttribute(mm_tf32_kernel<1>, cudaFuncAttributeMaxDynamicSharedMemorySize, SMEM_BYTES);
        cudaFuncSetAttribute(mm_tf32_kernel<2>, cudaFuncAttributeMaxDynamicSharedMemorySize, SMEM_BYTES);
        init_done = true;
    }

    // fork: CSR construction on side stream, concurrent with QKV GEMM
    cudaEventRecord(ev_fork, 0);
    cudaStreamWaitEvent(s_side, ev_fork, 0);

    // 1) fused QKV projections (TF32 tensor cores), one launch, grid.z = 3
    mm_tf32_kernel<0><<<dim3(GX, 1, 3), 128, SMEM_BYTES>>>(
        feat, DIM, N_NODES, Wq, Wk, Wv, DIM, qkv, QKV_LD, DIM,
        nullptr, nullptr, nullptr, nullptr, nullptr);

    // 2) CSR by dst (side stream)
    cudaMemsetAsync(curp, 0, N_NODES * sizeof(int), s_side);
    hist_kernel<<<(E + 255) / 256, 256, 0, s_side>>>(dst, E);
    scan_blk_kernel<<<NSB, SB, 0, s_side>>>(N_NODES);
    scan_part_kernel<<<1, SB, 0, s_side>>>(NSB, N_NODES);
    scan_add_kernel<<<NSB, SB, 0, s_side>>>(N_NODES);
    scatter_kernel<<<(E + 255) / 256, 256, 0, s_side>>>(src, dst, E);

    // join
    cudaEventRecord(ev_join, s_side);
    cudaStreamWaitEvent(0, ev_join, 0);

    // 3) online-softmax attention + residual + LN1 (warp per dst node)
    attn_ln1_kernel<<<(N_NODES * 32 + 255) / 256, 256>>>(feat, ln1g, ln1b);

    // 4) FFN1: h = PReLU(rst@W1 + b1)
    mm_tf32_kernel<1><<<dim3(GX, HID / GBN, 1), 128, SMEM_BYTES>>>(
        rst, DIM, PAD_N, W1, W1, W1, HID, hbuf, HID, DIM,
        b1, prelu, nullptr, nullptr, nullptr);

    // 5) FFN2 + bias + residual + LN2 -> out (fused epilogue)
    mm_tf32_kernel<2><<<dim3(GX, 1, 1), 128, SMEM_BYTES>>>(
        hbuf, HID, PAD_N, W2, W2, W2, DIM, out, DIM, HID,
        b2, nullptr, rst, ln2g, ln2b);
}

// round 8
// speedup vs baseline: 1.9115x; 1.9115x over previous
#include <cuda_runtime.h>
#include <cuda_fp16.h>
#include <mma.h>
#include <math.h>

using namespace nvcuda;

#define N_NODES 40000
#define PAD_N   40064            // 313 * 128
#define N_EDGES 640000
#define DIM     128
#define QKV_LD  384
#define HID     512
#define LN_EPS  1e-5f

// ---------------- scratch (device globals; no allocation allowed) ----------
static __device__ __half g_qkv [(size_t)PAD_N * QKV_LD]; // [q|k|v] per node (half)
static __device__ __half g_feat_h[(size_t)N_NODES * DIM];// feat as half (GEMM A)
static __device__ float  g_rst [(size_t)PAD_N * DIM];    // post-LN1 (float, residual)
static __device__ __half g_rst_h[(size_t)PAD_N * DIM];   // post-LN1 (half, FFN1 A)
static __device__ __half g_h   [(size_t)PAD_N * HID];    // FFN hidden (half)
static __device__ __half g_wqkv_h[3 * 128 * 128];        // Wq,Wk,Wv as half [k][n]
static __device__ __half g_w1_h[128 * 512];              // W1 half [k][n]
static __device__ __half g_w2_h[512 * 128];              // W2 half [k][n]
static __device__ int    g_off[N_NODES + 1];             // CSR offsets (by dst)
static __device__ int    g_cur[N_NODES];                 // counts / cursors
static __device__ int    g_esrc[N_EDGES];                // src ids sorted by dst
static __device__ int    g_part[256];                    // scan partials

// ---------------- cp.async helpers -----------------------------------------
__device__ __forceinline__ void cp16(void* smem, const void* gmem)
{
    unsigned s = (unsigned)__cvta_generic_to_shared(smem);
    asm volatile("cp.async.ca.shared.global [%0], [%1], 16;\n" :: "r"(s), "l"(gmem));
}
__device__ __forceinline__ void cp16z(void* smem, const void* gmem, bool pred)
{
    unsigned s = (unsigned)__cvta_generic_to_shared(smem);
    int sz = pred ? 16 : 0;   // src-size 0 => zero-fill 16B, no gmem access
    asm volatile("cp.async.ca.shared.global [%0], [%1], 16, %2;\n"
                 :: "r"(s), "l"(gmem), "r"(sz));
}
#define CP_COMMIT() asm volatile("cp.async.commit_group;\n" ::)
#define CP_WAIT(n)  asm volatile("cp.async.wait_group %0;\n" :: "n"(n))

// ---------------- FP16 WMMA GEMM: C[M,N] = A[M,K] @ B[K,N] ------------------
// A, B half; accumulate fp32. Tile BM=128, BN=128, BK=32, 2-stage cp.async,
// 8 warps in 4x2; warp tile 32x64 (2x4 wmma 16x16x16). 2 blocks/SM.
// EPI: 0 = half store (QKV: B selected by blockIdx.z, C col offset z*128)
//      1 = +bias then PReLU, half store
//      2 = +bias +residual, per-row LayerNorm -> float out (row guard)
#define GBM 128
#define GBN 128
#define GBK 32
#define AS_H (GBM * 40)            // halfs per stage (pad 32->40)
#define BS_H (GBK * 136)           // halfs per stage (pad 128->136)
#define STG_H (AS_H + BS_H)        // 9472 halfs = 18944 B
#define CS_BYTES (128 * 132 * 4)   // 67584 B epilogue staging
#define SMEM_BYTES CS_BYTES        // > 2*STG_H*2 = 37888

template <int EPI>
__global__ __launch_bounds__(256, 2)
void mm_h_kernel(const __half* __restrict__ A, int lda, int Mlim,
                 const __half* __restrict__ B0,
                 const __half* __restrict__ B1,
                 const __half* __restrict__ B2, int ldb,
                 void* __restrict__ Cout, int ldc, int K,
                 const float* __restrict__ bias,
                 const float* __restrict__ pw,
                 const float* __restrict__ res,
                 const float* __restrict__ lng,
                 const float* __restrict__ lnb)
{
    extern __shared__ __align__(16) char smc[];
    float (*Cs)[132] = (float(*)[132]) smc;       // epilogue reuse

    const int tid = threadIdx.x;
    const int wid = tid >> 5;
    const int rowBase = blockIdx.x * GBM;
    const int colBaseB = blockIdx.y * GBN;
    const int z = blockIdx.z;
    const __half* B = (z == 0) ? B0 : (z == 1) ? B1 : B2;
    const int colBaseC = colBaseB + z * 128;

    const int wm = wid >> 1;            // 0..3 -> warp row0 = wm*32
    const int wn = wid & 1;             // 0..1 -> warp col0 = wn*64

    wmma::fragment<wmma::accumulator, 16, 16, 16, float> acc[2][4];
#pragma unroll
    for (int i = 0; i < 2; i++)
#pragma unroll
        for (int j = 0; j < 4; j++) wmma::fill_fragment(acc[i][j], 0.f);

    const int ar = tid >> 2;            // 0..63 (2 passes of 64 rows)
    const int ac = (tid & 3) * 8;       // 0,8,16,24 (halfs)
    const int br = tid >> 4;            // 0..15 (2 passes of 16 rows)
    const int bc = (tid & 15) * 8;      // 0..120 (halfs)

    const __half* Abase = A + (size_t)rowBase * lda;
    const __half* Bbase = B + colBaseB;

    auto issue = [&](int st, int k0) {
        __half* As = (__half*)smc + st * STG_H;
        __half* Bs = As + AS_H;
#pragma unroll
        for (int p = 0; p < 2; p++) {
            const int r = ar + p * 64;
            cp16z(As + r * 40 + ac, Abase + (size_t)r * lda + k0 + ac,
                  rowBase + r < Mlim);
        }
#pragma unroll
        for (int p = 0; p < 2; p++) {
            const int r = br + p * 16;
            cp16(Bs + r * 136 + bc, Bbase + (size_t)(k0 + r) * ldb + bc);
        }
        CP_COMMIT();
    };

    const int nIter = K / GBK;          // 4 or 16
    issue(0, 0);

    for (int it = 0; it < nIter; it++) {
        const bool more = (it + 1 < nIter);
        if (more) issue((it + 1) & 1, (it + 1) * GBK);
        if (more) { CP_WAIT(1); } else { CP_WAIT(0); }
        __syncthreads();

        const __half* As = (const __half*)smc + (it & 1) * STG_H;
        const __half* Bs = As + AS_H;
#pragma unroll
        for (int kk = 0; kk < GBK; kk += 16) {
            wmma::fragment<wmma::matrix_a, 16, 16, 16, __half, wmma::row_major> fa[2];
            wmma::fragment<wmma::matrix_b, 16, 16, 16, __half, wmma::row_major> fb[4];
#pragma unroll
            for (int i = 0; i < 2; i++)
                wmma::load_matrix_sync(fa[i], As + (wm * 32 + i * 16) * 40 + kk, 40);
#pragma unroll
            for (int j = 0; j < 4; j++)
                wmma::load_matrix_sync(fb[j], Bs + kk * 136 + wn * 64 + j * 16, 136);
#pragma unroll
            for (int i = 0; i < 2; i++)
#pragma unroll
                for (int j = 0; j < 4; j++)
                    wmma::mma_sync(acc[i][j], fa[i], fb[j], acc[i][j]);
        }
        __syncthreads();
    }

    // stage C tile in shared (float)
#pragma unroll
    for (int i = 0; i < 2; i++)
#pragma unroll
        for (int j = 0; j < 4; j++)
            wmma::store_matrix_sync(&Cs[wm * 32 + i * 16][wn * 64 + j * 16],
                                    acc[i][j], 132, wmma::mem_row_major);
    __syncthreads();

    if (EPI == 0) {
        __half* C = (__half*)Cout;
#pragma unroll
        for (int it = 0; it < 16; it++) {
            const int lin = tid + it * 256;      // f4 index over 128x32
            const int r = lin >> 5, c4 = (lin & 31) * 4;
            float4 v = *(const float4*)&Cs[r][c4];
            __half* dstp = C + (size_t)(rowBase + r) * ldc + colBaseC + c4;
            *(__half2*)(dstp)     = __floats2half2_rn(v.x, v.y);
            *(__half2*)(dstp + 2) = __floats2half2_rn(v.z, v.w);
        }
    } else if (EPI == 1) {
        __half* C = (__half*)Cout;
#pragma unroll
        for (int it = 0; it < 16; it++) {
            const int lin = tid + it * 256;
            const int r = lin >> 5, c4 = (lin & 31) * 4;
            float4 v = *(const float4*)&Cs[r][c4];
            const float4 bi = *(const float4*)(bias + colBaseC + c4);
            const float4 pv = *(const float4*)(pw + colBaseC + c4);
            v.x += bi.x; v.y += bi.y; v.z += bi.z; v.w += bi.w;
            v.x = v.x >= 0.f ? v.x : pv.x * v.x;
            v.y = v.y >= 0.f ? v.y : pv.y * v.y;
            v.z = v.z >= 0.f ? v.z : pv.z * v.z;
            v.w = v.w >= 0.f ? v.w : pv.w * v.w;
            __half* dstp = C + (size_t)(rowBase + r) * ldc + colBaseC + c4;
            *(__half2*)(dstp)     = __floats2half2_rn(v.x, v.y);
            *(__half2*)(dstp + 2) = __floats2half2_rn(v.z, v.w);
        }
    } else {  // EPI == 2 : +bias +residual, per-row LayerNorm -> float out
        float* C = (float*)Cout;
        const int lane = tid & 31;
        const int col = lane * 4;
        const float4 bi = *(const float4*)(bias + col);
        const float4 g4 = *(const float4*)(lng + col);
        const float4 b4 = *(const float4*)(lnb + col);
#pragma unroll
        for (int rr = 0; rr < 16; rr++) {
            const int r = wid * 16 + rr;
            const int grow = rowBase + r;
            float4 v = *(const float4*)&Cs[r][col];
            const float4 rs = *(const float4*)(res + (size_t)grow * DIM + col);
            float x0 = v.x + bi.x + rs.x;
            float x1 = v.y + bi.y + rs.y;
            float x2 = v.z + bi.z + rs.z;
            float x3 = v.w + bi.w + rs.w;
            float sum = x0 + x1 + x2 + x3;
            float sq = x0 * x0 + x1 * x1 + x2 * x2 + x3 * x3;
#pragma unroll
            for (int o = 16; o; o >>= 1) {
                sum += __shfl_xor_sync(0xffffffffu, sum, o);
                sq  += __shfl_xor_sync(0xffffffffu, sq, o);
            }
            const float mu = sum * (1.f / DIM);
            const float var = sq * (1.f / DIM) - mu * mu;
            const float rstd = rsqrtf(var + LN_EPS);
            float4 o4;
            o4.x = (x0 - mu) * rstd * g4.x + b4.x;
            o4.y = (x1 - mu) * rstd * g4.y + b4.y;
            o4.z = (x2 - mu) * rstd * g4.z + b4.z;
            o4.w = (x3 - mu) * rstd * g4.w + b4.w;
            if (grow < N_NODES)
                *(float4*)(C + (size_t)grow * DIM + col) = o4;
        }
    }
}

// ---------------- dtype conversion kernels ----------------------------------
__global__ void cvt_feat_kernel(const float* __restrict__ feat)
{
    int i = blockIdx.x * blockDim.x + threadIdx.x;   // float4 index
    if (i >= N_NODES * DIM / 4) return;
    float4 v = *(const float4*)(feat + i * 4);
    __half* d = g_feat_h + i * 4;
    *(__half2*)(d)     = __floats2half2_rn(v.x, v.y);
    *(__half2*)(d + 2) = __floats2half2_rn(v.z, v.w);
}
__global__ void cvt_wqkv_kernel(const float* __restrict__ Wq,
                                const float* __restrict__ Wk,
                                const float* __restrict__ Wv)
{
    int i = blockIdx.x * blockDim.x + threadIdx.x;
    if (i >= 3 * 128 * 128) return;
    const int h = i >> 14, r = i & 16383;
    const float* W = (h == 0) ? Wq : (h == 1) ? Wk : Wv;
    g_wqkv_h[i] = __float2half(W[r]);
}
__global__ void cvt_w1_kernel(const float* __restrict__ W1)
{
    int i = blockIdx.x * blockDim.x + threadIdx.x;
    if (i < 128 * 512) g_w1_h[i] = __float2half(W1[i]);
}
__global__ void cvt_w2_kernel(const float* __restrict__ W2)
{
    int i = blockIdx.x * blockDim.x + threadIdx.x;
    if (i < 512 * 128) g_w2_h[i] = __float2half(W2[i]);
}

// ---------------- CSR construction -----------------------------------------
__global__ void hist_kernel(const int* __restrict__ dst, int e)
{
    int i = blockIdx.x * blockDim.x + threadIdx.x;
    if (i < e) atomicAdd(&g_cur[dst[i]], 1);
}

#define SB 256
#define NSB ((N_NODES + SB - 1) / SB)   // 157

__global__ __launch_bounds__(SB)
void scan_blk_kernel(int n)
{
    __shared__ int sh[SB];
    const int t = threadIdx.x;
    const int i = blockIdx.x * SB + t;
    const int v = (i < n) ? g_cur[i] : 0;
    sh[t] = v;
    __syncthreads();
    for (int o = 1; o < SB; o <<= 1) {
        int x = (t >= o) ? sh[t - o] : 0;
        __syncthreads();
        sh[t] += x;
        __syncthreads();
    }
    if (i < n) g_off[i] = sh[t] - v;
    if (t == SB - 1) g_part[blockIdx.x] = sh[t];
}

__global__ __launch_bounds__(SB)
void scan_part_kernel(int nb, int n)
{
    __shared__ int sh[SB];
    const int t = threadIdx.x;
    const int v = (t < nb) ? g_part[t] : 0;
    sh[t] = v;
    __syncthreads();
    for (int o = 1; o < SB; o <<= 1) {
        int x = (t >= o) ? sh[t - o] : 0;
        __syncthreads();
        sh[t] += x;
        __syncthreads();
    }
    if (t < nb) g_part[t] = sh[t] - v;
    if (t == SB - 1) g_off[n] = sh[t];
}

__global__ __launch_bounds__(SB)
void scan_add_kernel(int n)
{
    const int i = blockIdx.x * SB + threadIdx.x;
    if (i < n) {
        const int o = g_off[i] + g_part[blockIdx.x];
        g_off[i] = o;
        g_cur[i] = o;
    }
}

__global__ void scatter_kernel(const int* __restrict__ src,
                               const int* __restrict__ dst, int e)
{
    int i = blockIdx.x * blockDim.x + threadIdx.x;
    if (i < e) {
        int p = atomicAdd(&g_cur[dst[i]], 1);
        g_esrc[p] = src[i];
    }
}

// ---------------- attention (warp per dst node, online softmax) + LN1 ------
__device__ __forceinline__ float4 ld_half4(const __half* p)
{
    const __half2 h0 = *(const __half2*)(p);
    const __half2 h1 = *(const __half2*)(p + 2);
    const float2 a = __half22float2(h0);
    const float2 b = __half22float2(h1);
    return make_float4(a.x, a.y, b.x, b.y);
}

__device__ __forceinline__ void attn_step(float4 k4, float4 v4, float4 q4,
                                          float& m, float& s, float4& acc)
{
    float x = q4.x * k4.x + q4.y * k4.y + q4.z * k4.z + q4.w * k4.w;
    x += __shfl_xor_sync(0xffffffffu, x, 1);
    x += __shfl_xor_sync(0xffffffffu, x, 2);
    x *= 0.08838834764831845f;              // 1/sqrt(DH*H) = 1/sqrt(128)
    const float nm = fmaxf(m, x);
    const float corr = __expf(m - nm);
    const float w = __expf(x - nm);
    s = s * corr + w;
    acc.x = acc.x * corr + w * v4.x;
    acc.y = acc.y * corr + w * v4.y;
    acc.z = acc.z * corr + w * v4.z;
    acc.w = acc.w * corr + w * v4.w;
    m = nm;
}

__global__ __launch_bounds__(256)
void attn_ln1_kernel(const float* __restrict__ feat,
                     const float* __restrict__ ln1g,
                     const float* __restrict__ ln1b)
{
    const int gw = (blockIdx.x * blockDim.x + threadIdx.x) >> 5;
    if (gw >= N_NODES) return;
    const int lane = threadIdx.x & 31;
    const int col = lane * 4;

    const float4 q4 = ld_half4(g_qkv + (size_t)gw * QKV_LD + col);

    float m = -INFINITY, s = 0.f;
    float4 acc = make_float4(0, 0, 0, 0);

    const int beg = g_off[gw], end = g_off[gw + 1];
    int t = beg;
    for (; t + 4 <= end; t += 4) {
        const int s0 = g_esrc[t],     s1 = g_esrc[t + 1];
        const int s2 = g_esrc[t + 2], s3 = g_esrc[t + 3];
        const __half* b0 = g_qkv + (size_t)s0 * QKV_LD + col;
        const __half* b1 = g_qkv + (size_t)s1 * QKV_LD + col;
        const __half* b2 = g_qkv + (size_t)s2 * QKV_LD + col;
        const __half* b3 = g_qkv + (size_t)s3 * QKV_LD + col;
        const float4 k0 = ld_half4(b0 + DIM);
        const float4 k1 = ld_half4(b1 + DIM);
        const float4 k2 = ld_half4(b2 + DIM);
        const float4 k3 = ld_half4(b3 + DIM);
        const float4 v0 = ld_half4(b0 + 2 * DIM);
        const float4 v1 = ld_half4(b1 + 2 * DIM);
        const float4 v2 = ld_half4(b2 + 2 * DIM);
        const float4 v3 = ld_half4(b3 + 2 * DIM);
        attn_step(k0, v0, q4, m, s, acc);
        attn_step(k1, v1, q4, m, s, acc);
        attn_step(k2, v2, q4, m, s, acc);
        attn_step(k3, v3, q4, m, s, acc);
    }
    for (; t < end; t++) {
        const __half* b = g_qkv + (size_t)g_esrc[t] * QKV_LD + col;
        const float4 k4 = ld_half4(b + DIM);
        const float4 v4 = ld_half4(b + 2 * DIM);
        attn_step(k4, v4, q4, m, s, acc);
    }

    const float inv = (s > 0.f) ? (1.f / s) : 0.f;
    const float4 f4 = *(const float4*)(feat + (size_t)gw * DIM + col);
    float x0 = acc.x * inv + f4.x;
    float x1 = acc.y * inv + f4.y;
    float x2 = acc.z * inv + f4.z;
    float x3 = acc.w * inv + f4.w;

    float sum = x0 + x1 + x2 + x3;
    float sq = x0 * x0 + x1 * x1 + x2 * x2 + x3 * x3;
#pragma unroll
    for (int o = 16; o; o >>= 1) {
        sum += __shfl_xor_sync(0xffffffffu, sum, o);
        sq  += __shfl_xor_sync(0xffffffffu, sq, o);
    }
    const float mu = sum * (1.f / DIM);
    const float var = sq * (1.f / DIM) - mu * mu;
    const float rstd = rsqrtf(var + LN_EPS);

    const float4 g4 = *(const float4*)(ln1g + col);
    const float4 b4 = *(const float4*)(ln1b + col);
    float4 o4;
    o4.x = (x0 - mu) * rstd * g4.x + b4.x;
    o4.y = (x1 - mu) * rstd * g4.y + b4.y;
    o4.z = (x2 - mu) * rstd * g4.z + b4.z;
    o4.w = (x3 - mu) * rstd * g4.w + b4.w;
    *(float4*)(g_rst + (size_t)gw * DIM + col) = o4;
    __half* rh = g_rst_h + (size_t)gw * DIM + col;
    *(__half2*)(rh)     = __floats2half2_rn(o4.x, o4.y);
    *(__half2*)(rh + 2) = __floats2half2_rn(o4.z, o4.w);
}

// ---------------- launch -----------------------------------------------------
extern "C" void kernel_launch(void* const* d_in, const int* in_sizes, int n_in,
                              void* d_out, int out_size)
{
    const float* feat  = (const float*)d_in[0];
    const int*   src   = (const int*)d_in[1];
    const int*   dst   = (const int*)d_in[2];
    const float* Wq    = (const float*)d_in[3];
    const float* Wk    = (const float*)d_in[4];
    const float* Wv    = (const float*)d_in[5];
    const float* ln1g  = (const float*)d_in[6];
    const float* ln1b  = (const float*)d_in[7];
    const float* ln2g  = (const float*)d_in[8];
    const float* ln2b  = (const float*)d_in[9];
    const float* W1    = (const float*)d_in[10];
    const float* b1    = (const float*)d_in[11];
    const float* prelu = (const float*)d_in[12];
    const float* W2    = (const float*)d_in[13];
    const float* b2    = (const float*)d_in[14];
    float* out = (float*)d_out;

    const int E = in_sizes[1];
    const int GX = PAD_N / GBM;   // 313

    void* p;
    __half *qkv, *feath, *rsth, *hbuf, *wqkvh, *w1h, *w2h;
    float *rst;
    int* curp;
    cudaGetSymbolAddress(&p, g_qkv);    qkv   = (__half*)p;
    cudaGetSymbolAddress(&p, g_feat_h); feath = (__half*)p;
    cudaGetSymbolAddress(&p, g_rst);    rst   = (float*)p;
    cudaGetSymbolAddress(&p, g_rst_h);  rsth  = (__half*)p;
    cudaGetSymbolAddress(&p, g_h);      hbuf  = (__half*)p;
    cudaGetSymbolAddress(&p, g_wqkv_h); wqkvh = (__half*)p;
    cudaGetSymbolAddress(&p, g_w1_h);   w1h   = (__half*)p;
    cudaGetSymbolAddress(&p, g_w2_h);   w2h   = (__half*)p;
    cudaGetSymbolAddress(&p, g_cur);    curp  = (int*)p;

    static bool init_done = false;
    static cudaStream_t s_side;
    static cudaEvent_t ev_fork, ev_join;
    if (!init_done) {
        cudaStreamCreateWithFlags(&s_side, cudaStreamNonBlocking);
        cudaEventCreateWithFlags(&ev_fork, cudaEventDisableTiming);
        cudaEventCreateWithFlags(&ev_join, cudaEventDisableTiming);
        cudaFuncSetAttribute(mm_h_kernel<0>, cudaFuncAttributeMaxDynamicSharedMemorySize, SMEM_BYTES);
        cudaFuncSetAttribute(mm_h_kernel<1>, cudaFuncAttributeMaxDynamicSharedMemorySize, SMEM_BYTES);
        cudaFuncSetAttribute(mm_h_kernel<2>, cudaFuncAttributeMaxDynamicSharedMemorySize, SMEM_BYTES);
        init_done = true;
    }

    // fork: CSR + FFN weight conversion on side stream, concurrent with QKV
    cudaEventRecord(ev_fork, 0);
    cudaStreamWaitEvent(s_side, ev_fork, 0);

    // main: convert feat + QKV weights to half, then fused QKV (fp16 HMMA)
    cvt_feat_kernel<<<(N_NODES * DIM / 4 + 255) / 256, 256>>>(feat);
    cvt_wqkv_kernel<<<192, 256>>>(Wq, Wk, Wv);
    mm_h_kernel<0><<<dim3(GX, 1, 3), 256, SMEM_BYTES>>>(
        feath, DIM, N_NODES, wqkvh, wqkvh + 16384, wqkvh + 32768, DIM,
        qkv, QKV_LD, DIM, nullptr, nullptr, nullptr, nullptr, nullptr);

    // side: FFN weight conversion + CSR by dst
    cvt_w1_kernel<<<256, 256, 0, s_side>>>(W1);
    cvt_w2_kernel<<<256, 256, 0, s_side>>>(W2);
    cudaMemsetAsync(curp, 0, N_NODES * sizeof(int), s_side);
    hist_kernel<<<(E + 255) / 256, 256, 0, s_side>>>(dst, E);
    scan_blk_kernel<<<NSB, SB, 0, s_side>>>(N_NODES);
    scan_part_kernel<<<1, SB, 0, s_side>>>(NSB, N_NODES);
    scan_add_kernel<<<NSB, SB, 0, s_side>>>(N_NODES);
    scatter_kernel<<<(E + 255) / 256, 256, 0, s_side>>>(src, dst, E);

    // join
    cudaEventRecord(ev_join, s_side);
    cudaStreamWaitEvent(0, ev_join, 0);

    // online-softmax attention + residual + LN1 (warp per dst node)
    attn_ln1_kernel<<<(N_NODES * 32 + 255) / 256, 256>>>(feat, ln1g, ln1b);

    // FFN1: h = PReLU(rst@W1 + b1)  (half in/out)
    mm_h_kernel<1><<<dim3(GX, HID / GBN, 1), 256, SMEM_BYTES>>>(
        rsth, DIM, N_NODES, w1h, w1h, w1h, HID,
        hbuf, HID, DIM, b1, prelu, nullptr, nullptr, nullptr);

    // FFN2 + bias + residual + LN2 -> float out (fused epilogue)
    mm_h_kernel<2><<<dim3(GX, 1, 1), 256, SMEM_BYTES>>>(
        hbuf, HID, PAD_N, w2h, w2h, w2h, DIM,
        out, DIM, HID, b2, nullptr, rst, ln2g, ln2b);
}

// round 9
// speedup vs baseline: 1.9312x; 1.0103x over previous
#include <cuda_runtime.h>
#include <cuda_fp16.h>
#include <mma.h>
#include <math.h>

using namespace nvcuda;

#define N_NODES 40000
#define PAD_N   40064            // 313 * 128
#define N_EDGES 640000
#define DIM     128
#define QKV_LD  384              // [q:128 | kv interleaved:256]
#define HID     512
#define LN_EPS  1e-5f

// ---------------- scratch (device globals; no allocation allowed) ----------
static __device__ __half g_qkv [(size_t)PAD_N * QKV_LD]; // [q | kv-interleaved]
static __device__ __half g_feat_h[(size_t)N_NODES * DIM];// feat as half (GEMM A)
static __device__ float  g_rst [(size_t)PAD_N * DIM];    // post-LN1 (float, residual)
static __device__ __half g_rst_h[(size_t)PAD_N * DIM];   // post-LN1 (half, FFN1 A)
static __device__ __half g_h   [(size_t)PAD_N * HID];    // FFN hidden (half)
static __device__ __half g_wqkv_h[3 * 128 * 128];        // Wq,Wk,Wv as half [k][n]
static __device__ __half g_w1_h[128 * 512];              // W1 half [k][n]
static __device__ __half g_w2_h[512 * 128];              // W2 half [k][n]
static __device__ int    g_off[N_NODES + 1];             // CSR offsets (by dst)
static __device__ int    g_cur[N_NODES];                 // counts / cursors
static __device__ int    g_esrc[N_EDGES];                // src ids sorted by dst
static __device__ int    g_part[256];                    // scan partials

// ---------------- cp.async helpers -----------------------------------------
__device__ __forceinline__ void cp16(void* smem, const void* gmem)
{
    unsigned s = (unsigned)__cvta_generic_to_shared(smem);
    asm volatile("cp.async.ca.shared.global [%0], [%1], 16;\n" :: "r"(s), "l"(gmem));
}
__device__ __forceinline__ void cp16z(void* smem, const void* gmem, bool pred)
{
    unsigned s = (unsigned)__cvta_generic_to_shared(smem);
    int sz = pred ? 16 : 0;   // src-size 0 => zero-fill 16B, no gmem access
    asm volatile("cp.async.ca.shared.global [%0], [%1], 16, %2;\n"
                 :: "r"(s), "l"(gmem), "r"(sz));
}
#define CP_COMMIT() asm volatile("cp.async.commit_group;\n" ::)
#define CP_WAIT(n)  asm volatile("cp.async.wait_group %0;\n" :: "n"(n))

// ---------------- FP16 WMMA GEMM: C[M,N] = A[M,K] @ B[K,N] ------------------
// A, B half; accumulate fp32. Tile BM=128, BN=128, BK=64, 2-stage cp.async,
// 8 warps in 4x2; warp tile 32x64 (2x4 wmma 16x16x16). 2 blocks/SM.
// EPI: 0 = QKV store: z=0 -> q cols, z=1/2 -> interleaved kv block
//      1 = +bias then PReLU, half store
//      2 = +bias +residual, per-row LayerNorm -> float out (row guard)
#define GBM 128
#define GBN 128
#define GBK 64
#define AS_H (GBM * 72)            // halfs per stage (pad 64->72)
#define BS_H (GBK * 136)           // halfs per stage (pad 128->136)
#define STG_H (AS_H + BS_H)        // 17920 halfs = 35840 B
#define CS_BYTES (128 * 132 * 4)   // 67584 B epilogue staging
#define SMEM_BYTES (2 * STG_H * 2) // 71680 B (> CS_BYTES)

template <int EPI>
__global__ __launch_bounds__(256, 2)
void mm_h_kernel(const __half* __restrict__ A, int lda, int Mlim,
                 const __half* __restrict__ B0,
                 const __half* __restrict__ B1,
                 const __half* __restrict__ B2, int ldb,
                 void* __restrict__ Cout, int ldc, int K,
                 const float* __restrict__ bias,
                 const float* __restrict__ pw,
                 const float* __restrict__ res,
                 const float* __restrict__ lng,
                 const float* __restrict__ lnb)
{
    extern __shared__ __align__(16) char smc[];
    float (*Cs)[132] = (float(*)[132]) smc;       // epilogue reuse

    const int tid = threadIdx.x;
    const int wid = tid >> 5;
    const int rowBase = blockIdx.x * GBM;
    const int colBaseB = blockIdx.y * GBN;
    const int z = blockIdx.z;
    const __half* B = (z == 0) ? B0 : (z == 1) ? B1 : B2;

    const int wm = wid >> 1;            // 0..3 -> warp row0 = wm*32
    const int wn = wid & 1;             // 0..1 -> warp col0 = wn*64

    wmma::fragment<wmma::accumulator, 16, 16, 16, float> acc[2][4];
#pragma unroll
    for (int i = 0; i < 2; i++)
#pragma unroll
        for (int j = 0; j < 4; j++) wmma::fill_fragment(acc[i][j], 0.f);

    const int ar = tid >> 3;            // 0..31 (4 passes of 32 rows)
    const int ac = (tid & 7) * 8;       // 0..56 (halfs)
    const int br = tid >> 4;            // 0..15 (4 passes of 16 rows)
    const int bc = (tid & 15) * 8;      // 0..120 (halfs)

    const __half* Abase = A + (size_t)rowBase * lda;
    const __half* Bbase = B + colBaseB;

    auto issue = [&](int st, int k0) {
        __half* As = (__half*)smc + st * STG_H;
        __half* Bs = As + AS_H;
#pragma unroll
        for (int p = 0; p < 4; p++) {
            const int r = ar + p * 32;
            cp16z(As + r * 72 + ac, Abase + (size_t)r * lda + k0 + ac,
                  rowBase + r < Mlim);
        }
#pragma unroll
        for (int p = 0; p < 4; p++) {
            const int r = br + p * 16;
            cp16(Bs + r * 136 + bc, Bbase + (size_t)(k0 + r) * ldb + bc);
        }
        CP_COMMIT();
    };

    const int nIter = K / GBK;          // 2 or 8
    issue(0, 0);

    for (int it = 0; it < nIter; it++) {
        const bool more = (it + 1 < nIter);
        if (more) issue((it + 1) & 1, (it + 1) * GBK);
        if (more) { CP_WAIT(1); } else { CP_WAIT(0); }
        __syncthreads();

        const __half* As = (const __half*)smc + (it & 1) * STG_H;
        const __half* Bs = As + AS_H;
#pragma unroll
        for (int kk = 0; kk < GBK; kk += 16) {
            wmma::fragment<wmma::matrix_a, 16, 16, 16, __half, wmma::row_major> fa[2];
            wmma::fragment<wmma::matrix_b, 16, 16, 16, __half, wmma::row_major> fb[4];
#pragma unroll
            for (int i = 0; i < 2; i++)
                wmma::load_matrix_sync(fa[i], As + (wm * 32 + i * 16) * 72 + kk, 72);
#pragma unroll
            for (int j = 0; j < 4; j++)
                wmma::load_matrix_sync(fb[j], Bs + kk * 136 + wn * 64 + j * 16, 136);
#pragma unroll
            for (int i = 0; i < 2; i++)
#pragma unroll
                for (int j = 0; j < 4; j++)
                    wmma::mma_sync(acc[i][j], fa[i], fb[j], acc[i][j]);
        }
        __syncthreads();
    }

    // stage C tile in shared (float)
#pragma unroll
    for (int i = 0; i < 2; i++)
#pragma unroll
        for (int j = 0; j < 4; j++)
            wmma::store_matrix_sync(&Cs[wm * 32 + i * 16][wn * 64 + j * 16],
                                    acc[i][j], 132, wmma::mem_row_major);
    __syncthreads();

    if (EPI == 0) {
        // QKV layout: row*384 + [q: c | k: 128+2*c4 | v: 128+2*c4+4]
        __half* C = (__half*)Cout;
#pragma unroll
        for (int it = 0; it < 16; it++) {
            const int lin = tid + it * 256;      // f4 index over 128x32
            const int r = lin >> 5, c4 = (lin & 31) * 4;
            float4 v = *(const float4*)&Cs[r][c4];
            __half2 h0 = __floats2half2_rn(v.x, v.y);
            __half2 h1 = __floats2half2_rn(v.z, v.w);
            __half* rowp = C + (size_t)(rowBase + r) * QKV_LD;
            __half* dstp = (z == 0) ? (rowp + c4)
                                    : (rowp + 128 + 2 * c4 + (z == 2 ? 4 : 0));
            *(__half2*)(dstp)     = h0;
            *(__half2*)(dstp + 2) = h1;
        }
    } else if (EPI == 1) {
        __half* C = (__half*)Cout;
        const int colBaseC = colBaseB;
#pragma unroll
        for (int it = 0; it < 16; it++) {
            const int lin = tid + it * 256;
            const int r = lin >> 5, c4 = (lin & 31) * 4;
            float4 v = *(const float4*)&Cs[r][c4];
            const float4 bi = *(const float4*)(bias + colBaseC + c4);
            const float4 pv = *(const float4*)(pw + colBaseC + c4);
            v.x += bi.x; v.y += bi.y; v.z += bi.z; v.w += bi.w;
            v.x = v.x >= 0.f ? v.x : pv.x * v.x;
            v.y = v.y >= 0.f ? v.y : pv.y * v.y;
            v.z = v.z >= 0.f ? v.z : pv.z * v.z;
            v.w = v.w >= 0.f ? v.w : pv.w * v.w;
            __half* dstp = C + (size_t)(rowBase + r) * ldc + colBaseC + c4;
            *(__half2*)(dstp)     = __floats2half2_rn(v.x, v.y);
            *(__half2*)(dstp + 2) = __floats2half2_rn(v.z, v.w);
        }
    } else {  // EPI == 2 : +bias +residual, per-row LayerNorm -> float out
        float* C = (float*)Cout;
        const int lane = tid & 31;
        const int col = lane * 4;
        const float4 bi = *(const float4*)(bias + col);
        const float4 g4 = *(const float4*)(lng + col);
        const float4 b4 = *(const float4*)(lnb + col);
#pragma unroll
        for (int rr = 0; rr < 16; rr++) {
            const int r = wid * 16 + rr;
            const int grow = rowBase + r;
            float4 v = *(const float4*)&Cs[r][col];
            const float4 rs = *(const float4*)(res + (size_t)grow * DIM + col);
            float x0 = v.x + bi.x + rs.x;
            float x1 = v.y + bi.y + rs.y;
            float x2 = v.z + bi.z + rs.z;
            float x3 = v.w + bi.w + rs.w;
            float sum = x0 + x1 + x2 + x3;
            float sq = x0 * x0 + x1 * x1 + x2 * x2 + x3 * x3;
#pragma unroll
            for (int o = 16; o; o >>= 1) {
                sum += __shfl_xor_sync(0xffffffffu, sum, o);
                sq  += __shfl_xor_sync(0xffffffffu, sq, o);
            }
            const float mu = sum * (1.f / DIM);
            const float var = sq * (1.f / DIM) - mu * mu;
            const float rstd = rsqrtf(var + LN_EPS);
            float4 o4;
            o4.x = (x0 - mu) * rstd * g4.x + b4.x;
            o4.y = (x1 - mu) * rstd * g4.y + b4.y;
            o4.z = (x2 - mu) * rstd * g4.z + b4.z;
            o4.w = (x3 - mu) * rstd * g4.w + b4.w;
            if (grow < N_NODES)
                *(float4*)(C + (size_t)grow * DIM + col) = o4;
        }
    }
}

// ---------------- dtype conversion kernels ----------------------------------
#define FEAT4 (N_NODES * DIM / 4)       // 1280000 float4s
__global__ void cvt_main_kernel(const float* __restrict__ feat,
                                const float* __restrict__ Wq,
                                const float* __restrict__ Wk,
                                const float* __restrict__ Wv)
{
    int i = blockIdx.x * blockDim.x + threadIdx.x;
    if (i < FEAT4) {
        float4 v = *(const float4*)(feat + i * 4);
        __half* d = g_feat_h + i * 4;
        *(__half2*)(d)     = __floats2half2_rn(v.x, v.y);
        *(__half2*)(d + 2) = __floats2half2_rn(v.z, v.w);
    } else {
        int j = i - FEAT4;
        if (j < 3 * 128 * 128) {
            const int h = j >> 14, r = j & 16383;
            const float* W = (h == 0) ? Wq : (h == 1) ? Wk : Wv;
            g_wqkv_h[j] = __float2half(W[r]);
        }
    }
}
__global__ void cvt_w1_kernel(const float* __restrict__ W1)
{
    int i = blockIdx.x * blockDim.x + threadIdx.x;
    if (i < 128 * 512) g_w1_h[i] = __float2half(W1[i]);
}
__global__ void cvt_w2_kernel(const float* __restrict__ W2)
{
    int i = blockIdx.x * blockDim.x + threadIdx.x;
    if (i < 512 * 128) g_w2_h[i] = __float2half(W2[i]);
}

// ---------------- CSR construction -----------------------------------------
__global__ void hist_kernel(const int* __restrict__ dst, int e)
{
    int i = blockIdx.x * blockDim.x + threadIdx.x;
    if (i < e) atomicAdd(&g_cur[dst[i]], 1);
}

#define SB 256
#define NSB ((N_NODES + SB - 1) / SB)   // 157

__global__ __launch_bounds__(SB)
void scan_blk_kernel(int n)
{
    __shared__ int sh[SB];
    const int t = threadIdx.x;
    const int i = blockIdx.x * SB + t;
    const int v = (i < n) ? g_cur[i] : 0;
    sh[t] = v;
    __syncthreads();
    for (int o = 1; o < SB; o <<= 1) {
        int x = (t >= o) ? sh[t - o] : 0;
        __syncthreads();
        sh[t] += x;
        __syncthreads();
    }
    if (i < n) g_off[i] = sh[t] - v;
    if (t == SB - 1) g_part[blockIdx.x] = sh[t];
}

__global__ __launch_bounds__(SB)
void scan_part_kernel(int nb, int n)
{
    __shared__ int sh[SB];
    const int t = threadIdx.x;
    const int v = (t < nb) ? g_part[t] : 0;
    sh[t] = v;
    __syncthreads();
    for (int o = 1; o < SB; o <<= 1) {
        int x = (t >= o) ? sh[t - o] : 0;
        __syncthreads();
        sh[t] += x;
        __syncthreads();
    }
    if (t < nb) g_part[t] = sh[t] - v;
    if (t == SB - 1) g_off[n] = sh[t];
}

__global__ __launch_bounds__(SB)
void scan_add_kernel(int n)
{
    const int i = blockIdx.x * SB + threadIdx.x;
    if (i < n) {
        const int o = g_off[i] + g_part[blockIdx.x];
        g_off[i] = o;
        g_cur[i] = o;
    }
}

__global__ void scatter_kernel(const int* __restrict__ src,
                               const int* __restrict__ dst, int e)
{
    int i = blockIdx.x * blockDim.x + threadIdx.x;
    if (i < e) {
        int p = atomicAdd(&g_cur[dst[i]], 1);
        g_esrc[p] = src[i];
    }
}

// ---------------- attention (warp per dst node, online softmax) + LN1 ------
// kv interleaved: one 16B load yields k4 (halfs 0-3) and v4 (halfs 4-7)
__device__ __forceinline__ void kv_unpack(uint4 raw, float4& k4, float4& v4)
{
    float2 a = __half22float2(*(const __half2*)&raw.x);
    float2 b = __half22float2(*(const __half2*)&raw.y);
    float2 c = __half22float2(*(const __half2*)&raw.z);
    float2 d = __half22float2(*(const __half2*)&raw.w);
    k4 = make_float4(a.x, a.y, b.x, b.y);
    v4 = make_float4(c.x, c.y, d.x, d.y);
}

__device__ __forceinline__ float4 ld_half4(const __half* p)
{
    const __half2 h0 = *(const __half2*)(p);
    const __half2 h1 = *(const __half2*)(p + 2);
    const float2 a = __half22float2(h0);
    const float2 b = __half22float2(h1);
    return make_float4(a.x, a.y, b.x, b.y);
}

__device__ __forceinline__ void attn_step(float4 k4, float4 v4, float4 q4,
                                          float& m, float& s, float4& acc)
{
    float x = q4.x * k4.x + q4.y * k4.y + q4.z * k4.z + q4.w * k4.w;
    x += __shfl_xor_sync(0xffffffffu, x, 1);
    x += __shfl_xor_sync(0xffffffffu, x, 2);
    x *= 0.08838834764831845f;              // 1/sqrt(DH*H) = 1/sqrt(128)
    const float nm = fmaxf(m, x);
    const float corr = __expf(m - nm);
    const float w = __expf(x - nm);
    s = s * corr + w;
    acc.x = acc.x * corr + w * v4.x;
    acc.y = acc.y * corr + w * v4.y;
    acc.z = acc.z * corr + w * v4.z;
    acc.w = acc.w * corr + w * v4.w;
    m = nm;
}

__global__ __launch_bounds__(256)
void attn_ln1_kernel(const float* __restrict__ feat,
                     const float* __restrict__ ln1g,
                     const float* __restrict__ ln1b)
{
    const int gw = (blockIdx.x * blockDim.x + threadIdx.x) >> 5;
    if (gw >= N_NODES) return;
    const int lane = threadIdx.x & 31;
    const int col = lane * 4;

    const float4 q4 = ld_half4(g_qkv + (size_t)gw * QKV_LD + col);

    float m = -INFINITY, s = 0.f;
    float4 acc = make_float4(0, 0, 0, 0);

    const int beg = g_off[gw], end = g_off[gw + 1];
    int t = beg;
    for (; t + 4 <= end; t += 4) {
        const int s0 = g_esrc[t],     s1 = g_esrc[t + 1];
        const int s2 = g_esrc[t + 2], s3 = g_esrc[t + 3];
        const uint4 r0 = *(const uint4*)(g_qkv + (size_t)s0 * QKV_LD + 128 + lane * 8);
        const uint4 r1 = *(const uint4*)(g_qkv + (size_t)s1 * QKV_LD + 128 + lane * 8);
        const uint4 r2 = *(const uint4*)(g_qkv + (size_t)s2 * QKV_LD + 128 + lane * 8);
        const uint4 r3 = *(const uint4*)(g_qkv + (size_t)s3 * QKV_LD + 128 + lane * 8);
        float4 k4, v4;
        kv_unpack(r0, k4, v4); attn_step(k4, v4, q4, m, s, acc);
        kv_unpack(r1, k4, v4); attn_step(k4, v4, q4, m, s, acc);
        kv_unpack(r2, k4, v4); attn_step(k4, v4, q4, m, s, acc);
        kv_unpack(r3, k4, v4); attn_step(k4, v4, q4, m, s, acc);
    }
    for (; t < end; t++) {
        const uint4 r = *(const uint4*)(g_qkv + (size_t)g_esrc[t] * QKV_LD + 128 + lane * 8);
        float4 k4, v4;
        kv_unpack(r, k4, v4);
        attn_step(k4, v4, q4, m, s, acc);
    }

    const float inv = (s > 0.f) ? (1.f / s) : 0.f;
    const float4 f4 = *(const float4*)(feat + (size_t)gw * DIM + col);
    float x0 = acc.x * inv + f4.x;
    float x1 = acc.y * inv + f4.y;
    float x2 = acc.z * inv + f4.z;
    float x3 = acc.w * inv + f4.w;

    float sum = x0 + x1 + x2 + x3;
    float sq = x0 * x0 + x1 * x1 + x2 * x2 + x3 * x3;
#pragma unroll
    for (int o = 16; o; o >>= 1) {
        sum += __shfl_xor_sync(0xffffffffu, sum, o);
        sq  += __shfl_xor_sync(0xffffffffu, sq, o);
    }
    const float mu = sum * (1.f / DIM);
    const float var = sq * (1.f / DIM) - mu * mu;
    const float rstd = rsqrtf(var + LN_EPS);

    const float4 g4 = *(const float4*)(ln1g + col);
    const float4 b4 = *(const float4*)(ln1b + col);
    float4 o4;
    o4.x = (x0 - mu) * rstd * g4.x + b4.x;
    o4.y = (x1 - mu) * rstd * g4.y + b4.y;
    o4.z = (x2 - mu) * rstd * g4.z + b4.z;
    o4.w = (x3 - mu) * rstd * g4.w + b4.w;
    *(float4*)(g_rst + (size_t)gw * DIM + col) = o4;
    __half* rh = g_rst_h + (size_t)gw * DIM + col;
    *(__half2*)(rh)     = __floats2half2_rn(o4.x, o4.y);
    *(__half2*)(rh + 2) = __floats2half2_rn(o4.z, o4.w);
}

// ---------------- launch -----------------------------------------------------
extern "C" void kernel_launch(void* const* d_in, const int* in_sizes, int n_in,
                              void* d_out, int out_size)
{
    const float* feat  = (const float*)d_in[0];
    const int*   src   = (const int*)d_in[1];
    const int*   dst   = (const int*)d_in[2];
    const float* Wq    = (const float*)d_in[3];
    const float* Wk    = (const float*)d_in[4];
    const float* Wv    = (const float*)d_in[5];
    const float* ln1g  = (const float*)d_in[6];
    const float* ln1b  = (const float*)d_in[7];
    const float* ln2g  = (const float*)d_in[8];
    const float* ln2b  = (const float*)d_in[9];
    const float* W1    = (const float*)d_in[10];
    const float* b1    = (const float*)d_in[11];
    const float* prelu = (const float*)d_in[12];
    const float* W2    = (const float*)d_in[13];
    const float* b2    = (const float*)d_in[14];
    float* out = (float*)d_out;

    const int E = in_sizes[1];
    const int GX = PAD_N / GBM;   // 313

    void* p;
    __half *qkv, *feath, *rsth, *hbuf, *wqkvh, *w1h, *w2h;
    float *rst;
    int* curp;
    cudaGetSymbolAddress(&p, g_qkv);    qkv   = (__half*)p;
    cudaGetSymbolAddress(&p, g_feat_h); feath = (__half*)p;
    cudaGetSymbolAddress(&p, g_rst);    rst   = (float*)p;
    cudaGetSymbolAddress(&p, g_rst_h);  rsth  = (__half*)p;
    cudaGetSymbolAddress(&p, g_h);      hbuf  = (__half*)p;
    cudaGetSymbolAddress(&p, g_wqkv_h); wqkvh = (__half*)p;
    cudaGetSymbolAddress(&p, g_w1_h);   w1h   = (__half*)p;
    cudaGetSymbolAddress(&p, g_w2_h);   w2h   = (__half*)p;
    cudaGetSymbolAddress(&p, g_cur);    curp  = (int*)p;

    static bool init_done = false;
    static cudaStream_t s_side;
    static cudaEvent_t ev_fork, ev_join;
    if (!init_done) {
        cudaStreamCreateWithFlags(&s_side, cudaStreamNonBlocking);
        cudaEventCreateWithFlags(&ev_fork, cudaEventDisableTiming);
        cudaEventCreateWithFlags(&ev_join, cudaEventDisableTiming);
        cudaFuncSetAttribute(mm_h_kernel<0>, cudaFuncAttributeMaxDynamicSharedMemorySize, SMEM_BYTES);
        cudaFuncSetAttribute(mm_h_kernel<1>, cudaFuncAttributeMaxDynamicSharedMemorySize, SMEM_BYTES);
        cudaFuncSetAttribute(mm_h_kernel<2>, cudaFuncAttributeMaxDynamicSharedMemorySize, SMEM_BYTES);
        init_done = true;
    }

    // fork: CSR + FFN weight conversion on side stream, concurrent with QKV
    cudaEventRecord(ev_fork, 0);
    cudaStreamWaitEvent(s_side, ev_fork, 0);

    // main: convert feat + QKV weights to half (one launch), then fused QKV
    cvt_main_kernel<<<(FEAT4 + 3 * 128 * 128 + 255) / 256, 256>>>(feat, Wq, Wk, Wv);
    mm_h_kernel<0><<<dim3(GX, 1, 3), 256, SMEM_BYTES>>>(
        feath, DIM, N_NODES, wqkvh, wqkvh + 16384, wqkvh + 32768, DIM,
        qkv, QKV_LD, DIM, nullptr, nullptr, nullptr, nullptr, nullptr);

    // side: FFN weight conversion + CSR by dst
    cvt_w1_kernel<<<256, 256, 0, s_side>>>(W1);
    cvt_w2_kernel<<<256, 256, 0, s_side>>>(W2);
    cudaMemsetAsync(curp, 0, N_NODES * sizeof(int), s_side);
    hist_kernel<<<(E + 255) / 256, 256, 0, s_side>>>(dst, E);
    scan_blk_kernel<<<NSB, SB, 0, s_side>>>(N_NODES);
    scan_part_kernel<<<1, SB, 0, s_side>>>(NSB, N_NODES);
    scan_add_kernel<<<NSB, SB, 0, s_side>>>(N_NODES);
    scatter_kernel<<<(E + 255) / 256, 256, 0, s_side>>>(src, dst, E);

    // join
    cudaEventRecord(ev_join, s_side);
    cudaStreamWaitEvent(0, ev_join, 0);

    // online-softmax attention + residual + LN1 (warp per dst node)
    attn_ln1_kernel<<<(N_NODES * 32 + 255) / 256, 256>>>(feat, ln1g, ln1b);

    // FFN1: h = PReLU(rst@W1 + b1)  (half in/out)
    mm_h_kernel<1><<<dim3(GX, HID / GBN, 1), 256, SMEM_BYTES>>>(
        rsth, DIM, N_NODES, w1h, w1h, w1h, HID,
        hbuf, HID, DIM, b1, prelu, nullptr, nullptr, nullptr);

    // FFN2 + bias + residual + LN2 -> float out (fused epilogue)
    mm_h_kernel<2><<<dim3(GX, 1, 1), 256, SMEM_BYTES>>>(
        hbuf, HID, PAD_N, w2h, w2h, w2h, DIM,
        out, DIM, HID, b2, nullptr, rst, ln2g, ln2b);
}